// round 4
// baseline (speedup 1.0000x reference)
#include <cuda_runtime.h>
#include <math.h>
#include <stdint.h>

// ---------------- problem constants ----------------
#define BB   128
#define TT   1024
#define II   256
#define HH   512
#define OO   256
#define LOUT 64
#define NCTA 128          // 16 clusters x 8 CTAs

#define WOP  514          // padded W_out smem row stride (floats)
#define XS   130          // xproj smem row stride (floats)

// smem sizes
#define XPROJ_SMEM (2 * 64 * XS * 4)                                  // 66560 B
// k_rnn smem floats: hbuf 2*4096, part 2048, wouts 32*WOP, sbhh 512, sbih 512, sbout 256
#define RNN_FLOATS (8192 + 2048 + 32*WOP + 512 + 512 + 256)
#define RNN_SMEM   (RNN_FLOATS * 4)                                   // 111872 B

// ---------------- device scratch ----------------
__device__ float g_xproj[(size_t)BB * TT * HH];   // 256 MB: x @ W_ih^T + b_ih

union U64 { unsigned long long u; float2 f; };

// Blackwell packed fp32 FMA (2 FMAs/instr; ptxas never auto-emits this)
__device__ __forceinline__ void ffma2(U64 &d, U64 a, U64 b) {
    asm("fma.rn.f32x2 %0, %1, %2, %0;" : "+l"(d.u) : "l"(a.u), "l"(b.u));
}

__device__ __forceinline__ uint32_t smem_u32(const void* p) {
    return (uint32_t)__cvta_generic_to_shared(p);
}

#define CLUSTER_SYNC() do { \
    asm volatile("barrier.cluster.arrive.aligned;" ::: "memory"); \
    asm volatile("barrier.cluster.wait.aligned;"   ::: "memory"); \
} while (0)

// ============================================================================
// Kernel 1: x_proj[b,t,h] = x[b,t,:] . W_ih[h,:] + b_ih[h]   (unchanged, passed)
// ============================================================================
__global__ void __launch_bounds__(256, 2)
k_xproj(const float* __restrict__ x, const int* __restrict__ lengths,
        const float* __restrict__ W_ih, const float* __restrict__ b_ih)
{
    extern __shared__ float sm[];
    float* xs = sm;                // [64][XS]
    float* ws = sm + 64 * XS;      // [64][XS]

    const int b  = blockIdx.z;
    const int t0 = blockIdx.y * 64;
    const int h0 = blockIdx.x * 64;
    if (t0 >= lengths[b]) return;

    const int tid = threadIdx.x;
    const int tr  = tid >> 4;
    const int tc  = tid & 15;

    U64 acc[4][4];
    #pragma unroll
    for (int i = 0; i < 4; i++)
        #pragma unroll
        for (int j = 0; j < 4; j++) acc[i][j].u = 0ULL;

    for (int kc = 0; kc < 2; kc++) {
        __syncthreads();
        #pragma unroll
        for (int i = 0; i < 16; i++) {
            int e = tid + 256 * i;
            int r = e >> 6, cc = e & 63;
            float2 xv = *(const float2*)(x + ((size_t)b * TT + t0 + r) * II + kc * 128 + 2 * cc);
            *(float2*)(xs + r * XS + 2 * cc) = xv;
            float2 wv = *(const float2*)(W_ih + (size_t)(h0 + r) * II + kc * 128 + 2 * cc);
            *(float2*)(ws + r * XS + 2 * cc) = wv;
        }
        __syncthreads();
        #pragma unroll 4
        for (int kp = 0; kp < 64; kp++) {
            U64 xf[4], wf[4];
            #pragma unroll
            for (int i = 0; i < 4; i++) xf[i].f = *(const float2*)(xs + (tr + 16*i) * XS + 2 * kp);
            #pragma unroll
            for (int j = 0; j < 4; j++) wf[j].f = *(const float2*)(ws + (tc + 16*j) * XS + 2 * kp);
            #pragma unroll
            for (int i = 0; i < 4; i++)
                #pragma unroll
                for (int j = 0; j < 4; j++) ffma2(acc[i][j], xf[i], wf[j]);
        }
    }

    #pragma unroll
    for (int i = 0; i < 4; i++)
        #pragma unroll
        for (int j = 0; j < 4; j++) {
            int t = t0 + tr + 16 * i;
            int h = h0 + tc + 16 * j;
            g_xproj[((size_t)b * TT + t) * HH + h] = acc[i][j].f.x + acc[i][j].f.y + b_ih[h];
        }
}

// ============================================================================
// Kernel 2: clustered persistent RNN.
// 16 clusters x 8 CTAs. Cluster rg owns batch rows rg*8..+8 (independent of
// all other clusters -> per-cluster early exit at tmax). CTA cg owns columns
// cg*64..+64; thread (c = tid&63, kq = tid>>6) holds W_hh[col_c, kq*128..+128]
// in 64 U64 registers. Every CTA keeps a full replicated h (8 rows x 512) in
// smem, double-buffered; column owners push updates to all 8 ranks via
// st.shared::cluster; one barrier.cluster per step. h never touches DRAM/L2.
// ============================================================================
__global__ void __launch_bounds__(256, 1) __cluster_dims__(8, 1, 1)
k_rnn(const int* __restrict__ lengths, const float* __restrict__ W_hh,
      const float* __restrict__ b_hh, const float* __restrict__ b_ih,
      const float* __restrict__ W_out, const float* __restrict__ b_out,
      float* __restrict__ out)
{
    extern __shared__ float sm[];
    float* hb    = sm;                 // [2][8][512] double-buffered full h
    float* part  = sm + 8192;          // [4][512] k-split partials
    float* wouts = part + 2048;        // [32][WOP] W_out slice
    float* sbhh  = wouts + 32 * WOP;   // [512]
    float* sbih  = sbhh + 512;         // [512]
    float* sbout = sbih + 512;         // [256]

    const int tid    = threadIdx.x;
    const int cta    = blockIdx.x;
    const int rg     = cta >> 3;       // cluster id 0..15
    const int cg     = cta & 7;        // cluster rank 0..7
    const int c      = tid & 63;
    const int kq     = tid >> 6;       // 0..3
    const int b_base = rg * 8;
    const int col_c  = cg * 64 + c;
    const int r0     = tid >> 6;       // rows r0, r0+4 in reduce phase

    // --- DSMEM peer base addresses for hb (one mapa per rank, hoisted) ---
    uint32_t peer[8];
    {
        uint32_t hbase = smem_u32(hb);
        #pragma unroll
        for (int rk = 0; rk < 8; rk++)
            asm("mapa.shared::cluster.u32 %0, %1, %2;" : "=r"(peer[rk]) : "r"(hbase), "r"(rk));
    }

    // --- W_hh slice -> registers (permanent) ---
    U64 W[64];
    {
        const float2* wsrc = (const float2*)(W_hh + (size_t)col_c * HH + kq * 128);
        #pragma unroll
        for (int j = 0; j < 64; j++) W[j].f = wsrc[j];
    }

    // --- stage biases + W_out slice; zero h0 ---
    for (int i = tid; i < 512; i += 256) { sbhh[i] = b_hh[i]; sbih[i] = b_ih[i]; }
    sbout[tid] = b_out[tid];
    #pragma unroll
    for (int i = 0; i < 32; i++) {
        int e = tid + 256 * i;
        int r = e >> 8, cc = e & 255;
        float2 v = *(const float2*)(W_out + (size_t)(cg * 32 + r) * HH + 2 * cc);
        *(float2*)(wouts + r * WOP + 2 * cc) = v;
    }
    #pragma unroll
    for (int i = 0; i < 16; i++) hb[tid + 256 * i] = 0.f;   // zero hb[0] (4096 floats)

    int L[8];
    int tmax = 0;
    #pragma unroll
    for (int r = 0; r < 8; r++) { L[r] = lengths[b_base + r]; tmax = max(tmax, L[r]); }

    __syncthreads();
    CLUSTER_SYNC();

    int cur = 0;

    // =================== encoder (runs only to this cluster's tmax) ===========
    for (int t = 0; t < tmax; t++) {
        const int nxt = cur ^ 1;

        // prefetch xp for this thread's two outputs (DRAM latency overlaps GEMM)
        float xp0 = g_xproj[((size_t)(b_base + r0    ) * TT + t) * HH + col_c];
        float xp1 = g_xproj[((size_t)(b_base + r0 + 4) * TT + t) * HH + col_c];

        // GEMM: active rows only; h read from local replicated buffer (broadcast LDS)
        #pragma unroll 1
        for (int r = 0; r < 8; r++) {
            if (t < L[r]) {
                const float4* h4 = (const float4*)(hb + cur * 4096 + r * 512 + kq * 128);
                U64 a0, a1; a0.u = 0ULL; a1.u = 0ULL;
                #pragma unroll
                for (int j = 0; j < 32; j++) {
                    float4 p = h4[j];
                    U64 u0, u1;
                    u0.f.x = p.x; u0.f.y = p.y;
                    u1.f.x = p.z; u1.f.y = p.w;
                    ffma2(a0, u0, W[2 * j]);
                    ffma2(a1, u1, W[2 * j + 1]);
                }
                part[kq * 512 + r * 64 + c] = a0.f.x + a0.f.y + a1.f.x + a1.f.y;
            }
        }
        __syncthreads();

        // reduce + tanh + push to all 8 ranks
        #pragma unroll
        for (int q = 0; q < 2; q++) {
            int r = r0 + 4 * q;
            if (t < L[r]) {
                int o = r * 64 + c;
                float s = part[o] + part[512 + o] + part[1024 + o] + part[1536 + o]
                        + (q ? xp1 : xp0) + sbhh[col_c];
                float v = tanhf(s);
                uint32_t off = (uint32_t)(nxt * 4096 + r * 512 + col_c) * 4u;
                #pragma unroll
                for (int rk = 0; rk < 8; rk++)
                    asm volatile("st.shared::cluster.f32 [%0], %1;"
                                 :: "r"(peer[rk] + off), "f"(v) : "memory");
            }
        }

        // frozen rows: local copy cur->nxt (all CTAs hold identical replicas)
        #pragma unroll 1
        for (int r = 0; r < 8; r++) {
            if (t >= L[r] && tid < 128) {
                float4 v = *(const float4*)(hb + cur * 4096 + r * 512 + tid * 4);
                *(float4*)(hb + nxt * 4096 + r * 512 + tid * 4) = v;
            }
        }

        CLUSTER_SYNC();   // release our DSMEM pushes; acquire peers'
        cur = nxt;
    }

    // =================== decoder (64 steps, all rows active) ==================
    for (int s = 0; s < LOUT; s++) {
        const int nxt = cur ^ 1;

        #pragma unroll 1
        for (int r = 0; r < 8; r++) {
            const float4* h4 = (const float4*)(hb + cur * 4096 + r * 512 + kq * 128);
            U64 a0, a1; a0.u = 0ULL; a1.u = 0ULL;
            #pragma unroll
            for (int j = 0; j < 32; j++) {
                float4 p = h4[j];
                U64 u0, u1;
                u0.f.x = p.x; u0.f.y = p.y;
                u1.f.x = p.z; u1.f.y = p.w;
                ffma2(a0, u0, W[2 * j]);
                ffma2(a1, u1, W[2 * j + 1]);
            }
            part[kq * 512 + r * 64 + c] = a0.f.x + a0.f.y + a1.f.x + a1.f.y;
        }
        __syncthreads();

        #pragma unroll
        for (int q = 0; q < 2; q++) {
            int r = r0 + 4 * q;
            int o = r * 64 + c;
            float sv = part[o] + part[512 + o] + part[1024 + o] + part[1536 + o]
                     + sbih[col_c] + sbhh[col_c];
            float v = tanhf(sv);
            uint32_t off = (uint32_t)(nxt * 4096 + r * 512 + col_c) * 4u;
            #pragma unroll
            for (int rk = 0; rk < 8; rk++)
                asm volatile("st.shared::cluster.f32 [%0], %1;"
                             :: "r"(peer[rk] + off), "f"(v) : "memory");
        }

        CLUSTER_SYNC();
        cur = nxt;

        // out[b, s, cg*32..+32] from the (now complete) local h
        {
            const int rr = tid >> 5;       // 0..7 batch row
            const int oo = tid & 31;       // 0..31 output col
            const float4* h4o = (const float4*)(hb + cur * 4096 + rr * 512);
            const float2* w2  = (const float2*)(wouts + oo * WOP);
            U64 a0, a1; a0.u = 0ULL; a1.u = 0ULL;
            #pragma unroll 4
            for (int j = 0; j < 128; j++) {
                float4 p = h4o[j];
                U64 u0, u1, w0, w1;
                u0.f.x = p.x; u0.f.y = p.y;
                u1.f.x = p.z; u1.f.y = p.w;
                w0.f = w2[2 * j];
                w1.f = w2[2 * j + 1];
                ffma2(a0, u0, w0);
                ffma2(a1, u1, w1);
            }
            float val = a0.f.x + a0.f.y + a1.f.x + a1.f.y + sbout[cg * 32 + oo];
            out[((size_t)(b_base + rr) * LOUT + s) * OO + cg * 32 + oo] = val;
        }
        // next h-GEMM reads hb[cur] (unchanged) and rewrites part; all prior
        // part readers passed the cluster barrier above -> safe.
        __syncthreads();
    }

    CLUSTER_SYNC();   // keep all cluster CTAs alive until DSMEM traffic is done
}

// ---------------- launch ----------------
extern "C" void kernel_launch(void* const* d_in, const int* in_sizes, int n_in,
                              void* d_out, int out_size)
{
    int k = 0;
    const float* x       = (const float*)d_in[k++];
    const int*   lengths = (const int*)  d_in[k++];
    if (k < n_in && in_sizes[k] == 1) k++;           // out_lengths scalar (if present)
    const float* W_ih    = (const float*)d_in[k++];
    const float* b_ih    = (const float*)d_in[k++];
    const float* W_hh    = (const float*)d_in[k++];
    const float* b_hh    = (const float*)d_in[k++];
    const float* W_out   = (const float*)d_in[k++];
    const float* b_out   = (const float*)d_in[k++];
    float* out = (float*)d_out;

    cudaFuncSetAttribute(k_xproj, cudaFuncAttributeMaxDynamicSharedMemorySize, XPROJ_SMEM);
    cudaFuncSetAttribute(k_rnn,   cudaFuncAttributeMaxDynamicSharedMemorySize, RNN_SMEM);

    dim3 g1(HH / 64, TT / 64, BB);   // (8, 16, 128)
    k_xproj<<<g1, 256, XPROJ_SMEM>>>(x, lengths, W_ih, b_ih);
    k_rnn<<<NCTA, 256, RNN_SMEM>>>(lengths, W_hh, b_hh, b_ih, W_out, b_out, out);
}

// round 5
// speedup vs baseline: 1.2615x; 1.2615x over previous
#include <cuda_runtime.h>
#include <math.h>
#include <stdint.h>

// ---------------- problem constants ----------------
#define BB   128
#define TT   1024
#define II   256
#define HH   512
#define OO   256
#define LOUT 64
#define NCTA 128          // 16 clusters x 8 CTAs

#define WOP  516          // W_out smem row stride (floats): 16B-aligned, bank-spread
#define XS   130          // xproj smem row stride

#define XPROJ_SMEM (2 * 64 * XS * 4)
// k_rnn smem floats: hb 2*4096, part 8*512, wouts 32*WOP, sbhh 512, sbih 512, sbout 256
#define RNN_FLOATS (8192 + 4096 + 32*WOP + 512 + 512 + 256)
#define RNN_SMEM   (RNN_FLOATS * 4)          // 120,320 B

__device__ float g_xproj[(size_t)BB * TT * HH];   // 256 MB scratch

union U64 { unsigned long long u; float2 f; };

__device__ __forceinline__ void ffma2(U64 &d, unsigned long long a, U64 b) {
    asm("fma.rn.f32x2 %0, %1, %2, %0;" : "+l"(d.u) : "l"(a), "l"(b.u));
}

__device__ __forceinline__ uint32_t smem_u32(const void* p) {
    return (uint32_t)__cvta_generic_to_shared(p);
}

#define CLUSTER_SYNC() do { \
    asm volatile("barrier.cluster.arrive.aligned;" ::: "memory"); \
    asm volatile("barrier.cluster.wait.aligned;"   ::: "memory"); \
} while (0)

// ============================================================================
// Kernel 1: x_proj = x @ W_ih^T + b_ih  (unchanged from passing R3 version)
// ============================================================================
__global__ void __launch_bounds__(256, 2)
k_xproj(const float* __restrict__ x, const int* __restrict__ lengths,
        const float* __restrict__ W_ih, const float* __restrict__ b_ih)
{
    extern __shared__ float sm[];
    float* xs = sm;
    float* ws = sm + 64 * XS;

    const int b  = blockIdx.z;
    const int t0 = blockIdx.y * 64;
    const int h0 = blockIdx.x * 64;
    if (t0 >= lengths[b]) return;

    const int tid = threadIdx.x;
    const int tr  = tid >> 4;
    const int tc  = tid & 15;

    U64 acc[4][4];
    #pragma unroll
    for (int i = 0; i < 4; i++)
        #pragma unroll
        for (int j = 0; j < 4; j++) acc[i][j].u = 0ULL;

    for (int kc = 0; kc < 2; kc++) {
        __syncthreads();
        #pragma unroll
        for (int i = 0; i < 16; i++) {
            int e = tid + 256 * i;
            int r = e >> 6, cc = e & 63;
            float2 xv = *(const float2*)(x + ((size_t)b * TT + t0 + r) * II + kc * 128 + 2 * cc);
            *(float2*)(xs + r * XS + 2 * cc) = xv;
            float2 wv = *(const float2*)(W_ih + (size_t)(h0 + r) * II + kc * 128 + 2 * cc);
            *(float2*)(ws + r * XS + 2 * cc) = wv;
        }
        __syncthreads();
        #pragma unroll 4
        for (int kp = 0; kp < 64; kp++) {
            U64 xf[4], wf[4];
            #pragma unroll
            for (int i = 0; i < 4; i++) xf[i].f = *(const float2*)(xs + (tr + 16*i) * XS + 2 * kp);
            #pragma unroll
            for (int j = 0; j < 4; j++) wf[j].f = *(const float2*)(ws + (tc + 16*j) * XS + 2 * kp);
            #pragma unroll
            for (int i = 0; i < 4; i++)
                #pragma unroll
                for (int j = 0; j < 4; j++) ffma2(acc[i][j], xf[i].u, wf[j]);
        }
    }

    #pragma unroll
    for (int i = 0; i < 4; i++)
        #pragma unroll
        for (int j = 0; j < 4; j++) {
            int t = t0 + tr + 16 * i;
            int h = h0 + tc + 16 * j;
            g_xproj[((size_t)b * TT + t) * HH + h] = acc[i][j].f.x + acc[i][j].f.y + b_ih[h];
        }
}

// ============================================================================
// Kernel 2: clustered persistent RNN, 512 threads/CTA.
// 16 clusters x 8 CTAs. Cluster rg owns batch rows rg*8..+8; CTA cg owns
// columns cg*64..+64. Thread: c = tid&63 (column), kq = tid>>6 (K-eighth,
// warp-uniform). W_hh[col][kq*64..+64] in 32 U64 regs. Thread also owns
// output (row = kq, col) in the reduce: 1 tanh + 8 DSMEM pushes.
// Frozen rows: never copied — per-row read parity = min(t, L[r]) & 1.
// One __syncthreads + one cluster barrier per step.
// ============================================================================
__global__ void __launch_bounds__(512, 1) __cluster_dims__(8, 1, 1)
k_rnn(const int* __restrict__ lengths, const float* __restrict__ W_hh,
      const float* __restrict__ b_hh, const float* __restrict__ b_ih,
      const float* __restrict__ W_out, const float* __restrict__ b_out,
      float* __restrict__ out)
{
    extern __shared__ float sm[];
    float* hb    = sm;                 // [2][8][512] double-buffered replicated h
    float* part  = sm + 8192;          // [8][512] k-split partials
    float* wouts = part + 4096;        // [32][WOP]
    float* sbhh  = wouts + 32 * WOP;   // [512]
    float* sbih  = sbhh + 512;         // [512]
    float* sbout = sbih + 512;         // [256]

    const int tid    = threadIdx.x;
    const int cta    = blockIdx.x;
    const int rg     = cta >> 3;
    const int cg     = cta & 7;
    const int c      = tid & 63;
    const int kq     = tid >> 6;       // 0..7, warp-uniform; also owned row
    const int b_base = rg * 8;
    const int col_c  = cg * 64 + c;

    // DSMEM peer bases for hb
    uint32_t peer[8];
    {
        uint32_t hbase = smem_u32(hb);
        #pragma unroll
        for (int rk = 0; rk < 8; rk++)
            asm("mapa.shared::cluster.u32 %0, %1, %2;" : "=r"(peer[rk]) : "r"(hbase), "r"(rk));
    }

    // W_hh[col_c][kq*64 .. +64] -> 32 U64 regs (permanent)
    U64 W[32];
    {
        const U64* wsrc = (const U64*)(W_hh + (size_t)col_c * HH + kq * 64);
        #pragma unroll
        for (int j = 0; j < 32; j++) W[j] = wsrc[j];
    }

    // stage biases + W_out slice; zero hb[0]
    if (tid < 512) { sbhh[tid] = b_hh[tid]; sbih[tid] = b_ih[tid]; }
    if (tid < 256) sbout[tid] = b_out[tid];
    #pragma unroll
    for (int i = 0; i < 16; i++) {                 // 8192 float2 of W_out
        int e = tid + 512 * i;
        int r = e >> 8, cc = e & 255;
        float2 v = *(const float2*)(W_out + (size_t)(cg * 32 + r) * HH + 2 * cc);
        *(float2*)(wouts + r * WOP + 2 * cc) = v;
    }
    #pragma unroll
    for (int i = 0; i < 8; i++) hb[tid + 512 * i] = 0.f;   // hb[0] = 0

    int L[8];
    int tmax = 0;
    #pragma unroll
    for (int r = 0; r < 8; r++) { L[r] = lengths[b_base + r]; tmax = max(tmax, L[r]); }
    const int L_own = L[kq];
    const float* xp_base = g_xproj + ((size_t)(b_base + kq) * TT) * HH + col_c;

    __syncthreads();
    CLUSTER_SYNC();

    // =================== encoder (to this cluster's tmax) =====================
    for (int t = 0; t < tmax; t++) {
        const int wp = (t + 1) & 1;

        // prefetch xp for owned output (consumed after GEMM -> latency hidden)
        float xp = 0.f;
        const bool own_act = (t < L_own);
        if (own_act) xp = xp_base[(size_t)t * HH];

        // GEMM: P[r] = W[col_c][k-chunk] . h[r][k-chunk], active rows only
        #pragma unroll
        for (int r = 0; r < 8; r++) {
            if (t < L[r]) {
                const ulonglong2* h2 = (const ulonglong2*)(hb + (t & 1) * 4096 + r * 512 + kq * 64);
                U64 a0, a1; a0.u = 0ULL; a1.u = 0ULL;
                #pragma unroll
                for (int j = 0; j < 16; j++) {
                    ulonglong2 q = h2[j];
                    ffma2(a0, q.x, W[2 * j]);
                    ffma2(a1, q.y, W[2 * j + 1]);
                }
                part[kq * 512 + r * 64 + c] = (a0.f.x + a1.f.x) + (a0.f.y + a1.f.y);
            }
        }
        __syncthreads();

        // reduce + tanh + distributed 8-rank push (thread owns row kq, col c)
        if (own_act) {
            float s = sbhh[col_c] + xp;
            #pragma unroll
            for (int k = 0; k < 8; k++) s += part[k * 512 + kq * 64 + c];
            float v = tanhf(s);
            uint32_t off = (uint32_t)(wp * 4096 + kq * 512 + col_c) * 4u;
            #pragma unroll
            for (int rk = 0; rk < 8; rk++)
                asm volatile("st.shared::cluster.f32 [%0], %1;"
                             :: "r"(peer[rk] + off), "f"(v) : "memory");
        }

        CLUSTER_SYNC();   // release pushes / acquire peers'; also syncs the CTA
    }

    // --- normalize: move rows whose last value sits in buffer 1 into buffer 0
    #pragma unroll
    for (int r = 0; r < 8; r++)
        if (L[r] & 1) hb[r * 512 + tid] = hb[4096 + r * 512 + tid];
    __syncthreads();
    CLUSTER_SYNC();       // no decoder push may land before local copies finish

    // =================== decoder (64 steps) ===================================
    for (int s = 0; s < LOUT; s++) {
        const int rp = s & 1, wp = rp ^ 1;

        #pragma unroll
        for (int r = 0; r < 8; r++) {
            const ulonglong2* h2 = (const ulonglong2*)(hb + rp * 4096 + r * 512 + kq * 64);
            U64 a0, a1; a0.u = 0ULL; a1.u = 0ULL;
            #pragma unroll
            for (int j = 0; j < 16; j++) {
                ulonglong2 q = h2[j];
                ffma2(a0, q.x, W[2 * j]);
                ffma2(a1, q.y, W[2 * j + 1]);
            }
            part[kq * 512 + r * 64 + c] = (a0.f.x + a1.f.x) + (a0.f.y + a1.f.y);
        }
        __syncthreads();

        {
            float sv = sbih[col_c] + sbhh[col_c];
            #pragma unroll
            for (int k = 0; k < 8; k++) sv += part[k * 512 + kq * 64 + c];
            float v = tanhf(sv);
            uint32_t off = (uint32_t)(wp * 4096 + kq * 512 + col_c) * 4u;
            #pragma unroll
            for (int rk = 0; rk < 8; rk++)
                asm volatile("st.shared::cluster.f32 [%0], %1;"
                             :: "r"(peer[rk] + off), "f"(v) : "memory");
        }

        CLUSTER_SYNC();   // new h (parity wp) complete in every replica

        // out[b, s, cg*32+oo] from new h; 256 threads, K=512
        if (tid < 256) {
            const int rr = tid >> 5;
            const int oo = tid & 31;
            const ulonglong2* h2 = (const ulonglong2*)(hb + wp * 4096 + rr * 512);
            const ulonglong2* w2 = (const ulonglong2*)(wouts + oo * WOP);
            U64 a0, a1; a0.u = 0ULL; a1.u = 0ULL;
            #pragma unroll 8
            for (int j = 0; j < 128; j++) {
                ulonglong2 qh = h2[j];
                ulonglong2 qw = w2[j];
                U64 wb0, wb1; wb0.u = qw.x; wb1.u = qw.y;
                ffma2(a0, qh.x, wb0);
                ffma2(a1, qh.y, wb1);
            }
            float val = (a0.f.x + a1.f.x) + (a0.f.y + a1.f.y) + sbout[cg * 32 + oo];
            out[((size_t)(b_base + rr) * LOUT + s) * OO + cg * 32 + oo] = val;
        }
        // safe: step s+1 pushes target parity rp (!= wp read here) and occur
        // only after the next cluster barrier, which needs our arrival.
    }

    CLUSTER_SYNC();   // keep cluster alive until all DSMEM traffic quiesces
}

// ---------------- launch ----------------
extern "C" void kernel_launch(void* const* d_in, const int* in_sizes, int n_in,
                              void* d_out, int out_size)
{
    int k = 0;
    const float* x       = (const float*)d_in[k++];
    const int*   lengths = (const int*)  d_in[k++];
    if (k < n_in && in_sizes[k] == 1) k++;           // out_lengths scalar (if present)
    const float* W_ih    = (const float*)d_in[k++];
    const float* b_ih    = (const float*)d_in[k++];
    const float* W_hh    = (const float*)d_in[k++];
    const float* b_hh    = (const float*)d_in[k++];
    const float* W_out   = (const float*)d_in[k++];
    const float* b_out   = (const float*)d_in[k++];
    float* out = (float*)d_out;

    cudaFuncSetAttribute(k_xproj, cudaFuncAttributeMaxDynamicSharedMemorySize, XPROJ_SMEM);
    cudaFuncSetAttribute(k_rnn,   cudaFuncAttributeMaxDynamicSharedMemorySize, RNN_SMEM);

    dim3 g1(HH / 64, TT / 64, BB);
    k_xproj<<<g1, 256, XPROJ_SMEM>>>(x, lengths, W_ih, b_ih);
    k_rnn<<<NCTA, 512, RNN_SMEM>>>(lengths, W_hh, b_hh, b_ih, W_out, b_out, out);
}